// round 4
// baseline (speedup 1.0000x reference)
#include <cuda_runtime.h>
#include <cstdint>
#include <cstddef>

// Problem constants
#define BB    16
#define TT    8192
#define DD    192
#define KC    512
#define SPAN  8
#define NSEG  16384
#define NTOK  131072

// Output packing: q_out [B,T,D] f32 | total_loss [1] | idx_out [B,T] | boundaries [B,T]
#define OFF_LOSS 25165824
#define OFF_IDX  25165825
#define OFF_BND  25296897

// k_argmin tiling: block = 128 segs x 128 codes, K streamed as 6 chunks of 32 dims
#define NCH       6
#define A_CH_U64  (32 * 128)      // dup {p,p} pairs per chunk
#define B_CH_F    (32 * 128)      // floats per B chunk (64 code-pairs * 2)
#define A_CH_B    32768
#define B_CH_B    16384
#define ARG_SMEM  (2 * (A_CH_B + B_CH_B))   // 98304 -> 2 blocks/SM

// Device scratch (no allocations allowed)
__device__ float  g_pooled[NSEG * DD];                    // [seg][d] for scatter
__device__ float2 g_pA[128 * NCH * A_CH_U64];             // [mtile][ch][d32][seg128] dup pairs
__device__ float  g_pB[4 * NCH * B_CH_F];                 // [ntile][ch][d32][pair64*2]
__device__ float  g_pnorm[NSEG];
__device__ unsigned long long g_best[NSEG];               // (enc(val)<<32)|idx via atomicMin
__device__ float  g_cbnorm[KC];
__device__ float  g_elatent;
__device__ int    g_bcount;

// ---------------------------------------------------------------------------
// helpers (all sm_100-base-safe PTX; proven compiling on this harness)
// ---------------------------------------------------------------------------
__device__ __forceinline__ unsigned smaddr(const void* p) {
    return (unsigned)__cvta_generic_to_shared(p);
}
__device__ __forceinline__ void mbar_init(unsigned a, unsigned cnt) {
    asm volatile("mbarrier.init.shared.b64 [%0], %1;" :: "r"(a), "r"(cnt) : "memory");
}
__device__ __forceinline__ void mbar_expect(unsigned a, unsigned bytes) {
    asm volatile("mbarrier.arrive.expect_tx.shared.b64 _, [%0], %1;" :: "r"(a), "r"(bytes) : "memory");
}
__device__ __forceinline__ void mbar_arrive(unsigned a) {
    asm volatile("mbarrier.arrive.shared.b64 _, [%0];" :: "r"(a) : "memory");
}
__device__ __forceinline__ void mbar_wait(unsigned a, unsigned par) {
    asm volatile(
        "{\n\t.reg .pred P;\n"
        "WL%=:\n\t"
        "mbarrier.try_wait.parity.acquire.cta.shared::cta.b64 P, [%0], %1;\n\t"
        "@!P bra WL%=;\n\t}"
        :: "r"(a), "r"(par) : "memory");
}
__device__ __forceinline__ void bulk_g2s(unsigned dst, const void* src, unsigned bytes, unsigned mbar) {
    asm volatile(
        "cp.async.bulk.shared::cluster.global.mbarrier::complete_tx::bytes [%0], [%1], %2, [%3];"
        :: "r"(dst), "l"(src), "r"(bytes), "r"(mbar) : "memory");
}
__device__ __forceinline__ void ffma2(unsigned long long& a, unsigned long long x, unsigned long long y) {
    asm("fma.rn.f32x2 %0, %1, %2, %0;" : "+l"(a) : "l"(x), "l"(y));
}

// ---------------------------------------------------------------------------
// K0: reset accumulators, g_best, codebook squared norms
// ---------------------------------------------------------------------------
__global__ void k_init(const float* __restrict__ cb) {
    int i = blockIdx.x * 256 + threadIdx.x;
    if (i == 0) { g_elatent = 0.f; g_bcount = 0; }
    if (i < NSEG) g_best[i] = ~0ull;
    if (i < KC) {
        const float4* r = (const float4*)(cb + (size_t)i * DD);
        float s = 0.f;
#pragma unroll
        for (int k = 0; k < DD / 4; k++) {
            float4 v = r[k];
            s += v.x * v.x + v.y * v.y + v.z * v.z + v.w * v.w;
        }
        g_cbnorm[i] = s;
    }
}

// ---------------------------------------------------------------------------
// K0b: pack codebook into pair image [ntile][ch][d32][pair64 * 2]
// ---------------------------------------------------------------------------
__global__ void __launch_bounds__(DD) k_prep(const float* __restrict__ cb) {
    int c = blockIdx.x, d = threadIdx.x;
    float v = cb[(size_t)c * DD + d];
    int nt = c >> 7;
    int within = c & 127;                       // pair = within>>1, half = within&1
    int idx = (((nt * NCH + (d >> 5)) * 32) + (d & 31)) * 128 + within;
    g_pB[idx] = v;                              // pairs are adjacent floats of a u64
}

// ---------------------------------------------------------------------------
// K1: segment pooling + pooled-norm + boundary predictor + duplicated A image
// ---------------------------------------------------------------------------
__global__ void __launch_bounds__(192) k_pool(const float* __restrict__ x,
                                              const float* __restrict__ w,
                                              const float* __restrict__ bbias,
                                              float* __restrict__ out_bnd) {
    int seg = blockIdx.x;
    int d   = threadIdx.x;
    const float* xp = x + (size_t)seg * (SPAN * DD) + d;
    float wd  = w[d];
    float part[SPAN];
    float sum = 0.f;
#pragma unroll
    for (int j = 0; j < SPAN; j++) {
        float v = xp[(size_t)j * DD];
        sum += v;
        part[j] = v * wd;
    }
    float p = sum * (1.0f / SPAN);
    g_pooled[(size_t)seg * DD + d] = p;

    // duplicated-pair A image for k_argmin
    {
        int mt = seg >> 7;
        int idx = (((mt * NCH + (d >> 5)) * 32) + (d & 31)) * 128 + (seg & 127);
        g_pA[idx] = make_float2(p, p);
    }

    float pn = p * p;
#pragma unroll
    for (int off = 16; off; off >>= 1) {
#pragma unroll
        for (int j = 0; j < SPAN; j++)
            part[j] += __shfl_down_sync(0xffffffffu, part[j], off);
        pn += __shfl_down_sync(0xffffffffu, pn, off);
    }
    __shared__ float sh[6][9];
    int wp = d >> 5, ln = d & 31;
    if (ln == 0) {
#pragma unroll
        for (int j = 0; j < SPAN; j++) sh[wp][j] = part[j];
        sh[wp][8] = pn;
    }
    __syncthreads();
    if (d < SPAN) {
        float z = bbias[0];
#pragma unroll
        for (int k = 0; k < 6; k++) z += sh[k][d];
        bool hi = z > 0.f;
        out_bnd[seg * SPAN + d] = hi ? 1.f : 0.f;
        unsigned bal = __ballot_sync(0x000000ffu, hi);
        if (d == 0) atomicAdd(&g_bcount, __popc(bal & 0xffu));
    } else if (d == SPAN) {
        float pn2 = 0.f;
#pragma unroll
        for (int k = 0; k < 6; k++) pn2 += sh[k][8];
        g_pnorm[seg] = pn2;
    }
}

// ---------------------------------------------------------------------------
// K2: VQ argmin via FFMA2 outer-product register tiling.
// Block = 128 segs (blockIdx.x) x 128 codes (blockIdx.y); 256 threads as a
// 16x16 grid, each thread 8 segs x 8 codes (32 u64 accumulators).
// K streamed as 6 chunks of 32 dims, cp.async.bulk double-buffered.
// Per d-step: 6 LDS.128 -> 32 FFMA2 (fma-pipe bound at occ 2).
// ---------------------------------------------------------------------------
__global__ void __launch_bounds__(256, 2) k_argmin() {
    extern __shared__ __align__(128) char sm[];
    __shared__ __align__(8) unsigned long long bar[4];  // full0 full1 empty0 empty1

    int tid = threadIdx.x;
    int tx  = tid & 15;     // code group: 8 codes = ntile*128 + tx*8 ..
    int ty  = tid >> 4;     // seg group:  8 segs  = mtile*128 + ty*8 ..
    int mt  = blockIdx.x;
    int nt  = blockIdx.y;

    unsigned full[2]  = { smaddr(&bar[0]), smaddr(&bar[1]) };
    unsigned empty[2] = { smaddr(&bar[2]), smaddr(&bar[3]) };
    unsigned smb = smaddr(sm);

    if (tid == 0) {
        mbar_init(full[0], 1);  mbar_init(full[1], 1);
        mbar_init(empty[0], 256); mbar_init(empty[1], 256);
        asm volatile("fence.proxy.async.shared::cta;" ::: "memory");
    }
    __syncthreads();

    if (tid == 0) {
#pragma unroll
        for (int ch = 0; ch < 2; ch++) {
            mbar_expect(full[ch], A_CH_B + B_CH_B);
            bulk_g2s(smb + ch * A_CH_B, &g_pA[(size_t)(mt * NCH + ch) * A_CH_U64], A_CH_B, full[ch]);
            bulk_g2s(smb + 2 * A_CH_B + ch * B_CH_B, &g_pB[(size_t)(nt * NCH + ch) * B_CH_F], B_CH_B, full[ch]);
        }
    }

    unsigned long long acc[8][4];
#pragma unroll
    for (int si = 0; si < 8; si++)
#pragma unroll
        for (int cj = 0; cj < 4; cj++) acc[si][cj] = 0ull;

    for (int ch = 0; ch < NCH; ch++) {
        int s = ch & 1;
        unsigned par = (ch >> 1) & 1;
        mbar_wait(full[s], par);

        const ulonglong2* a2 = (const ulonglong2*)(sm + s * A_CH_B);
        const ulonglong2* b2 = (const ulonglong2*)(sm + 2 * A_CH_B + s * B_CH_B);

#pragma unroll 4
        for (int d = 0; d < 32; d++) {
            ulonglong2 av[4], bv[2];
#pragma unroll
            for (int k = 0; k < 4; k++) av[k] = a2[d * 64 + ty * 4 + k];
#pragma unroll
            for (int k = 0; k < 2; k++) bv[k] = b2[d * 32 + tx * 2 + k];
#pragma unroll
            for (int si = 0; si < 8; si++) {
                unsigned long long pd = (si & 1) ? av[si >> 1].y : av[si >> 1].x;
                ffma2(acc[si][0], pd, bv[0].x);
                ffma2(acc[si][1], pd, bv[0].y);
                ffma2(acc[si][2], pd, bv[1].x);
                ffma2(acc[si][3], pd, bv[1].y);
            }
        }

        mbar_arrive(empty[s]);
        if (tid == 0 && ch + 2 < NCH) {
            mbar_wait(empty[s], par);
            int nch = ch + 2;
            mbar_expect(full[s], A_CH_B + B_CH_B);
            bulk_g2s(smb + s * A_CH_B, &g_pA[(size_t)(mt * NCH + nch) * A_CH_U64], A_CH_B, full[s]);
            bulk_g2s(smb + 2 * A_CH_B + s * B_CH_B, &g_pB[(size_t)(nt * NCH + nch) * B_CH_F], B_CH_B, full[s]);
        }
    }

    // epilogue: val = ||c||^2 - 2*dot; per-thread argmin over 8 codes per seg
    float cn[8];
#pragma unroll
    for (int j = 0; j < 8; j++) cn[j] = __ldg(&g_cbnorm[nt * 128 + tx * 8 + j]);

    float best[8];
    int   bidx[8];
#pragma unroll
    for (int si = 0; si < 8; si++) { best[si] = 3.4e38f; bidx[si] = 0; }

#pragma unroll
    for (int si = 0; si < 8; si++) {
#pragma unroll
        for (int cj = 0; cj < 4; cj++) {
            unsigned long long a = acc[si][cj];
            float lo = __uint_as_float((unsigned)a);
            float hi = __uint_as_float((unsigned)(a >> 32));
            int   c0 = nt * 128 + tx * 8 + cj * 2;
            float v0 = cn[cj * 2]     - 2.f * lo;
            float v1 = cn[cj * 2 + 1] - 2.f * hi;
            if (v0 < best[si] || (v0 == best[si] && c0 < bidx[si])) { best[si] = v0; bidx[si] = c0; }
            if (v1 < best[si] || (v1 == best[si] && (c0 + 1) < bidx[si])) { best[si] = v1; bidx[si] = c0 + 1; }
        }
    }

    // reduce across the 16 tx lanes sharing the same segs (xor stays in-group)
#pragma unroll
    for (int off = 1; off < 16; off <<= 1) {
#pragma unroll
        for (int si = 0; si < 8; si++) {
            float ov = __shfl_xor_sync(0xffffffffu, best[si], off);
            int   oi = __shfl_xor_sync(0xffffffffu, bidx[si], off);
            if (ov < best[si] || (ov == best[si] && oi < bidx[si])) {
                best[si] = ov; bidx[si] = oi;
            }
        }
    }
    if (tx == 0) {
#pragma unroll
        for (int si = 0; si < 8; si++) {
            int seg = mt * 128 + ty * 8 + si;
            unsigned fb  = __float_as_uint(best[si]);
            unsigned enc = (fb & 0x80000000u) ? ~fb : (fb | 0x80000000u);
            atomicMin(&g_best[seg], ((unsigned long long)enc << 32) | (unsigned)bidx[si]);
        }
    }
}

// ---------------------------------------------------------------------------
// K3: expand quantized segments (STE value p + (c - p)) + idx_out + e_latent
// ---------------------------------------------------------------------------
__global__ void __launch_bounds__(256) k_scatter(const float* __restrict__ cb,
                                                 float* __restrict__ q,
                                                 float* __restrict__ idxo) {
    __shared__ float bs;
    int tid = threadIdx.x;
    if (tid == 0) bs = 0.f;
    __syncthreads();

    int seg = blockIdx.x * 4 + (tid >> 6);
    int t   = tid & 63;
    unsigned long long v = g_best[seg];
    int idx = (int)(unsigned)(v & 0xffffffffu);
    if (t < 48) {
        float4 c4 = ((const float4*)(cb + (size_t)idx * DD))[t];
        float4 p4 = ((const float4*)(g_pooled + (size_t)seg * DD))[t];
        float4 o;
        o.x = p4.x + (c4.x - p4.x);
        o.y = p4.y + (c4.y - p4.y);
        o.z = p4.z + (c4.z - p4.z);
        o.w = p4.w + (c4.w - p4.w);
        float4* qp = (float4*)(q + (size_t)seg * (SPAN * DD)) + t;
#pragma unroll
        for (int j = 0; j < SPAN; j++) qp[j * (DD / 4)] = o;
    } else if (t < 48 + SPAN) {
        idxo[seg * SPAN + (t - 48)] = (float)idx;
    } else if (t == 56) {
        unsigned enc = (unsigned)(v >> 32);
        unsigned fb  = (enc & 0x80000000u) ? (enc ^ 0x80000000u) : ~enc;
        float dmin = __uint_as_float(fb);           // ||c||^2 - 2<p,c>
        atomicAdd(&bs, g_pnorm[seg] + dmin);        // + ||p||^2 = min d2
    }
    __syncthreads();
    if (tid == 0) atomicAdd(&g_elatent, bs);
}

// ---------------------------------------------------------------------------
// K4: finalize scalar loss
// ---------------------------------------------------------------------------
__global__ void k_final(float* __restrict__ loss_out) {
    float e  = g_elatent * (1.0f / ((float)NSEG * (float)DD));
    float br = (float)g_bcount * (1.0f / (float)NTOK);
    float bl = br - (1.0f / SPAN);
    loss_out[0] = 0.25f * e + 0.01f * bl * bl;
}

// ---------------------------------------------------------------------------
extern "C" void kernel_launch(void* const* d_in, const int* in_sizes, int n_in,
                              void* d_out, int out_size) {
    const float* x  = (const float*)d_in[0];
    const float* cb = (const float*)d_in[1];
    const float* w  = (const float*)d_in[2];
    const float* bb = (const float*)d_in[3];
    float* out  = (float*)d_out;
    float* q    = out;
    float* loss = out + OFF_LOSS;
    float* idxo = out + OFF_IDX;
    float* bnd  = out + OFF_BND;

    cudaFuncSetAttribute(k_argmin, cudaFuncAttributeMaxDynamicSharedMemorySize, ARG_SMEM);

    k_init<<<64, 256>>>(cb);
    k_prep<<<KC, DD>>>(cb);
    k_pool<<<NSEG, 192>>>(x, w, bb, bnd);
    k_argmin<<<dim3(128, 4), 256, ARG_SMEM>>>();
    k_scatter<<<NSEG / 4, 256>>>(cb, q, idxo);
    k_final<<<1, 1>>>(loss);
}

// round 5
// speedup vs baseline: 1.2407x; 1.2407x over previous
#include <cuda_runtime.h>
#include <cstdint>
#include <cstddef>

// Problem constants
#define BB    16
#define TT    8192
#define DD    192
#define KC    512
#define SPAN  8
#define NSEG  16384
#define NTOK  131072

// Output packing: q_out [B,T,D] f32 | total_loss [1] | idx_out [B,T] | boundaries [B,T]
#define OFF_LOSS 25165824
#define OFF_IDX  25165825
#define OFF_BND  25296897

// k_argmin tiling: block = 64 segs x 128 codes, 128 threads (8 segs x 8 codes each)
// K streamed as 12 chunks of 16 dims, double buffered.
#define NCH2      12
#define DCH       16
#define NMT       (NSEG / 64)      // 256 m-tiles
#define A_CH_B    8192             // 64 segs * 16 d * 8B (dup pairs)
#define B_CH_B    8192             // 128 codes * 16 d * 4B

// Device scratch (no allocations allowed)
__device__ float  g_pooled[NSEG * DD];                     // [seg][d] for scatter
__device__ float2 g_pA[NMT * NCH2 * DCH * 64];             // [mt][ch][d16][seg64] dup pairs
__device__ float  g_pB[4 * NCH2 * DCH * 128];              // [nt][ch][d16][code128]
__device__ float  g_pnorm[NSEG];
__device__ unsigned long long g_best[NSEG];                // (enc(val)<<32)|idx via atomicMin
__device__ float  g_cbnorm[KC];
__device__ float  g_elatent;
__device__ int    g_bcount;

// ---------------------------------------------------------------------------
// helpers (sm_100-base-safe PTX, proven on this harness)
// ---------------------------------------------------------------------------
__device__ __forceinline__ unsigned smaddr(const void* p) {
    return (unsigned)__cvta_generic_to_shared(p);
}
__device__ __forceinline__ void mbar_init(unsigned a, unsigned cnt) {
    asm volatile("mbarrier.init.shared.b64 [%0], %1;" :: "r"(a), "r"(cnt) : "memory");
}
__device__ __forceinline__ void mbar_expect(unsigned a, unsigned bytes) {
    asm volatile("mbarrier.arrive.expect_tx.shared.b64 _, [%0], %1;" :: "r"(a), "r"(bytes) : "memory");
}
__device__ __forceinline__ void mbar_arrive(unsigned a) {
    asm volatile("mbarrier.arrive.shared.b64 _, [%0];" :: "r"(a) : "memory");
}
__device__ __forceinline__ void mbar_wait(unsigned a, unsigned par) {
    asm volatile(
        "{\n\t.reg .pred P;\n"
        "WL%=:\n\t"
        "mbarrier.try_wait.parity.acquire.cta.shared::cta.b64 P, [%0], %1;\n\t"
        "@!P bra WL%=;\n\t}"
        :: "r"(a), "r"(par) : "memory");
}
__device__ __forceinline__ void bulk_g2s(unsigned dst, const void* src, unsigned bytes, unsigned mbar) {
    asm volatile(
        "cp.async.bulk.shared::cluster.global.mbarrier::complete_tx::bytes [%0], [%1], %2, [%3];"
        :: "r"(dst), "l"(src), "r"(bytes), "r"(mbar) : "memory");
}
__device__ __forceinline__ void ffma2(unsigned long long& a, unsigned long long x, unsigned long long y) {
    asm("fma.rn.f32x2 %0, %1, %2, %0;" : "+l"(a) : "l"(x), "l"(y));
}

// ---------------------------------------------------------------------------
// K0: fused init + codebook image prep.
// Grid = KC blocks x 192 threads. Block c: cbnorm[c], g_pB image row, and
// resets 32 g_best slots; block 0 resets scalars.
// ---------------------------------------------------------------------------
__global__ void __launch_bounds__(DD) k_prep(const float* __restrict__ cb) {
    int c = blockIdx.x, d = threadIdx.x;
    float v = cb[(size_t)c * DD + d];
    // pair image: [nt][ch][d16][code128]
    int nt = c >> 7;
    int idx = (((nt * NCH2 + (d >> 4)) * DCH) + (d & 15)) * 128 + (c & 127);
    g_pB[idx] = v;

    if (d < 32) g_best[c * 32 + d] = ~0ull;
    if (c == 0 && d == 0) { g_elatent = 0.f; g_bcount = 0; }

    float s = v * v;
#pragma unroll
    for (int off = 16; off; off >>= 1) s += __shfl_down_sync(0xffffffffu, s, off);
    __shared__ float sh[6];
    if ((d & 31) == 0) sh[d >> 5] = s;
    __syncthreads();
    if (d == 0) {
        float t = 0.f;
#pragma unroll
        for (int k = 0; k < 6; k++) t += sh[k];
        g_cbnorm[c] = t;
    }
}

// ---------------------------------------------------------------------------
// K1: segment pooling + pooled-norm + boundary predictor + duplicated A image
// ---------------------------------------------------------------------------
__global__ void __launch_bounds__(192) k_pool(const float* __restrict__ x,
                                              const float* __restrict__ w,
                                              const float* __restrict__ bbias,
                                              float* __restrict__ out_bnd) {
    int seg = blockIdx.x;
    int d   = threadIdx.x;
    const float* xp = x + (size_t)seg * (SPAN * DD) + d;
    float wd  = w[d];
    float part[SPAN];
    float sum = 0.f;
#pragma unroll
    for (int j = 0; j < SPAN; j++) {
        float v = xp[(size_t)j * DD];
        sum += v;
        part[j] = v * wd;
    }
    float p = sum * (1.0f / SPAN);
    g_pooled[(size_t)seg * DD + d] = p;

    // duplicated-pair A image: [mt][ch][d16][seg64]
    {
        int mt = seg >> 6;
        int idx = (((mt * NCH2 + (d >> 4)) * DCH) + (d & 15)) * 64 + (seg & 63);
        g_pA[idx] = make_float2(p, p);
    }

    float pn = p * p;
#pragma unroll
    for (int off = 16; off; off >>= 1) {
#pragma unroll
        for (int j = 0; j < SPAN; j++)
            part[j] += __shfl_down_sync(0xffffffffu, part[j], off);
        pn += __shfl_down_sync(0xffffffffu, pn, off);
    }
    __shared__ float sh[6][9];
    int wp = d >> 5, ln = d & 31;
    if (ln == 0) {
#pragma unroll
        for (int j = 0; j < SPAN; j++) sh[wp][j] = part[j];
        sh[wp][8] = pn;
    }
    __syncthreads();
    if (d < SPAN) {
        float z = bbias[0];
#pragma unroll
        for (int k = 0; k < 6; k++) z += sh[k][d];
        bool hi = z > 0.f;
        out_bnd[seg * SPAN + d] = hi ? 1.f : 0.f;
        unsigned bal = __ballot_sync(0x000000ffu, hi);
        if (d == 0) atomicAdd(&g_bcount, __popc(bal & 0xffu));
    } else if (d == SPAN) {
        float pn2 = 0.f;
#pragma unroll
        for (int k = 0; k < 6; k++) pn2 += sh[k][8];
        g_pnorm[seg] = pn2;
    }
}

// ---------------------------------------------------------------------------
// K2: VQ argmin, FFMA2 outer product with EXPLICIT software pipelining.
// Block = 64 segs (blockIdx.x) x 128 codes (blockIdx.y); 128 threads,
// tx=tid&15 -> 8 codes, ty=tid>>4 -> 8 segs. 12 chunks of 16 d, 2 stages.
// Per d-step: prefetch next step's 6 LDS.128 then issue 32 FFMA2 on current.
// ---------------------------------------------------------------------------
__global__ void __launch_bounds__(128, 4) k_argmin() {
    __shared__ __align__(16) char smA[2 * A_CH_B];
    __shared__ __align__(16) char smB[2 * B_CH_B];
    __shared__ __align__(8) unsigned long long bar[4];  // full0 full1 empty0 empty1

    int tid = threadIdx.x;
    int tx  = tid & 15;
    int ty  = tid >> 4;
    int mt  = blockIdx.x;
    int nt  = blockIdx.y;

    unsigned full[2]  = { smaddr(&bar[0]), smaddr(&bar[1]) };
    unsigned empty[2] = { smaddr(&bar[2]), smaddr(&bar[3]) };

    if (tid == 0) {
        mbar_init(full[0], 1);   mbar_init(full[1], 1);
        mbar_init(empty[0], 128); mbar_init(empty[1], 128);
        asm volatile("fence.proxy.async.shared::cta;" ::: "memory");
    }
    __syncthreads();

    if (tid == 0) {
#pragma unroll
        for (int ch = 0; ch < 2; ch++) {
            mbar_expect(full[ch], A_CH_B + B_CH_B);
            bulk_g2s(smaddr(smA + ch * A_CH_B), &g_pA[(size_t)(mt * NCH2 + ch) * (DCH * 64)], A_CH_B, full[ch]);
            bulk_g2s(smaddr(smB + ch * B_CH_B), &g_pB[(size_t)(nt * NCH2 + ch) * (DCH * 128)], B_CH_B, full[ch]);
        }
    }

    unsigned long long acc[8][4];
#pragma unroll
    for (int si = 0; si < 8; si++)
#pragma unroll
        for (int cj = 0; cj < 4; cj++) acc[si][cj] = 0ull;

    ulonglong2 av[2][4], bv[2][2];

#pragma unroll 1
    for (int ch = 0; ch < NCH2; ch++) {
        int s = ch & 1;
        unsigned par = (ch >> 1) & 1;
        mbar_wait(full[s], par);

        const ulonglong2* a2 = (const ulonglong2*)(smA + s * A_CH_B);
        const ulonglong2* b2 = (const ulonglong2*)(smB + s * B_CH_B);

        // preload d = 0
#pragma unroll
        for (int k = 0; k < 4; k++) av[0][k] = a2[ty * 4 + k];
#pragma unroll
        for (int k = 0; k < 2; k++) bv[0][k] = b2[tx * 2 + k];

#pragma unroll
        for (int d = 0; d < DCH; d++) {
            int cur = d & 1, nxt = cur ^ 1;
            if (d + 1 < DCH) {        // prefetch next step into the other set
#pragma unroll
                for (int k = 0; k < 4; k++) av[nxt][k] = a2[(d + 1) * 32 + ty * 4 + k];
#pragma unroll
                for (int k = 0; k < 2; k++) bv[nxt][k] = b2[(d + 1) * 32 + tx * 2 + k];
            }
#pragma unroll
            for (int si = 0; si < 8; si++) {
                unsigned long long pd = (si & 1) ? av[cur][si >> 1].y : av[cur][si >> 1].x;
                ffma2(acc[si][0], pd, bv[cur][0].x);
                ffma2(acc[si][1], pd, bv[cur][0].y);
                ffma2(acc[si][2], pd, bv[cur][1].x);
                ffma2(acc[si][3], pd, bv[cur][1].y);
            }
        }

        mbar_arrive(empty[s]);
        if (tid == 0 && ch + 2 < NCH2) {
            mbar_wait(empty[s], par);
            int nch = ch + 2;
            mbar_expect(full[s], A_CH_B + B_CH_B);
            bulk_g2s(smaddr(smA + s * A_CH_B), &g_pA[(size_t)(mt * NCH2 + nch) * (DCH * 64)], A_CH_B, full[s]);
            bulk_g2s(smaddr(smB + s * B_CH_B), &g_pB[(size_t)(nt * NCH2 + nch) * (DCH * 128)], B_CH_B, full[s]);
        }
    }

    // epilogue: val = ||c||^2 - 2*dot; per-thread argmin over 8 codes per seg
    float cn[8];
#pragma unroll
    for (int j = 0; j < 8; j++) cn[j] = __ldg(&g_cbnorm[nt * 128 + tx * 8 + j]);

    float best[8];
    int   bidx[8];
#pragma unroll
    for (int si = 0; si < 8; si++) { best[si] = 3.4e38f; bidx[si] = 0; }

#pragma unroll
    for (int si = 0; si < 8; si++) {
#pragma unroll
        for (int cj = 0; cj < 4; cj++) {
            unsigned long long a = acc[si][cj];
            float lo = __uint_as_float((unsigned)a);
            float hi = __uint_as_float((unsigned)(a >> 32));
            int   c0 = nt * 128 + tx * 8 + cj * 2;
            float v0 = cn[cj * 2]     - 2.f * lo;
            float v1 = cn[cj * 2 + 1] - 2.f * hi;
            if (v0 < best[si] || (v0 == best[si] && c0 < bidx[si])) { best[si] = v0; bidx[si] = c0; }
            if (v1 < best[si] || (v1 == best[si] && (c0 + 1) < bidx[si])) { best[si] = v1; bidx[si] = c0 + 1; }
        }
    }

    // reduce across the 16 tx lanes (xor offsets stay inside the half-warp)
#pragma unroll
    for (int off = 1; off < 16; off <<= 1) {
#pragma unroll
        for (int si = 0; si < 8; si++) {
            float ov = __shfl_xor_sync(0xffffffffu, best[si], off);
            int   oi = __shfl_xor_sync(0xffffffffu, bidx[si], off);
            if (ov < best[si] || (ov == best[si] && oi < bidx[si])) {
                best[si] = ov; bidx[si] = oi;
            }
        }
    }
    if (tx == 0) {
#pragma unroll
        for (int si = 0; si < 8; si++) {
            int seg = mt * 64 + ty * 8 + si;
            unsigned fb  = __float_as_uint(best[si]);
            unsigned enc = (fb & 0x80000000u) ? ~fb : (fb | 0x80000000u);
            atomicMin(&g_best[seg], ((unsigned long long)enc << 32) | (unsigned)bidx[si]);
        }
    }
}

// ---------------------------------------------------------------------------
// K3: expand quantized segments (STE value p + (c - p)) + idx_out + e_latent
// ---------------------------------------------------------------------------
__global__ void __launch_bounds__(256) k_scatter(const float* __restrict__ cb,
                                                 float* __restrict__ q,
                                                 float* __restrict__ idxo) {
    __shared__ float bs;
    int tid = threadIdx.x;
    if (tid == 0) bs = 0.f;
    __syncthreads();

    int seg = blockIdx.x * 4 + (tid >> 6);
    int t   = tid & 63;
    unsigned long long v = g_best[seg];
    int idx = (int)(unsigned)(v & 0xffffffffu);
    if (t < 48) {
        float4 c4 = ((const float4*)(cb + (size_t)idx * DD))[t];
        float4 p4 = ((const float4*)(g_pooled + (size_t)seg * DD))[t];
        float4 o;
        o.x = p4.x + (c4.x - p4.x);
        o.y = p4.y + (c4.y - p4.y);
        o.z = p4.z + (c4.z - p4.z);
        o.w = p4.w + (c4.w - p4.w);
        float4* qp = (float4*)(q + (size_t)seg * (SPAN * DD)) + t;
#pragma unroll
        for (int j = 0; j < SPAN; j++) qp[j * (DD / 4)] = o;
    } else if (t < 48 + SPAN) {
        idxo[seg * SPAN + (t - 48)] = (float)idx;
    } else if (t == 56) {
        unsigned enc = (unsigned)(v >> 32);
        unsigned fb  = (enc & 0x80000000u) ? (enc ^ 0x80000000u) : ~enc;
        float dmin = __uint_as_float(fb);           // ||c||^2 - 2<p,c>
        atomicAdd(&bs, g_pnorm[seg] + dmin);        // + ||p||^2 = min d2
    }
    __syncthreads();
    if (tid == 0) atomicAdd(&g_elatent, bs);
}

// ---------------------------------------------------------------------------
// K4: finalize scalar loss
// ---------------------------------------------------------------------------
__global__ void k_final(float* __restrict__ loss_out) {
    float e  = g_elatent * (1.0f / ((float)NSEG * (float)DD));
    float br = (float)g_bcount * (1.0f / (float)NTOK);
    float bl = br - (1.0f / SPAN);
    loss_out[0] = 0.25f * e + 0.01f * bl * bl;
}

// ---------------------------------------------------------------------------
extern "C" void kernel_launch(void* const* d_in, const int* in_sizes, int n_in,
                              void* d_out, int out_size) {
    const float* x  = (const float*)d_in[0];
    const float* cb = (const float*)d_in[1];
    const float* w  = (const float*)d_in[2];
    const float* bb = (const float*)d_in[3];
    float* out  = (float*)d_out;
    float* q    = out;
    float* loss = out + OFF_LOSS;
    float* idxo = out + OFF_IDX;
    float* bnd  = out + OFF_BND;

    k_prep<<<KC, DD>>>(cb);
    k_pool<<<NSEG, 192>>>(x, w, bb, bnd);
    k_argmin<<<dim3(NMT, 4), 128>>>();
    k_scatter<<<NSEG / 4, 256>>>(cb, q, idxo);
    k_final<<<1, 1>>>(loss);
}